// round 4
// baseline (speedup 1.0000x reference)
#include <cuda_runtime.h>

// ConvNearestNeightbor: out[b, n*C+c, h, w] = max_k |x_pad[b,c,h-row,w-col] - nb[n,c,k]|
// Issue-slot-bound at ~18.5 instr/output (floor 17). R4: raise issue% via occupancy
// (NSPLIT=4 -> 2048 blocks) + full n-loop unroll for LDS pipelining.

namespace {

constexpr int B = 16, C = 32, H = 32, W = 32, NUM = 32;
constexpr int HW = H * W;
constexpr int NSPLIT = 4;
constexpr int NPER = NUM / NSPLIT;  // 8

// max(|a|,|b|) -> single FMNMX with |src| modifiers on both operands
__device__ __forceinline__ float maxabs(float a, float b) {
  return fmaxf(fabsf(a), fabsf(b));
}

__global__ __launch_bounds__(256) void cnn_kernel(
    const float* __restrict__ x,
    const float* __restrict__ nb,
    float* __restrict__ out) {
  __shared__ __align__(16) float xs[34 * 36];      // halo tile, padded rows (36 floats)
  __shared__ __align__(16) float nbs[NPER * 12];   // 9 taps padded to 12 -> LDS.128

  const int bc = blockIdx.x;   // 0 .. B*C-1
  const int ns = blockIdx.y;   // 0 .. NSPLIT-1
  const int c  = bc & (C - 1);
  const int b  = bc / C;
  const int tid = threadIdx.x;

  const int h  = tid >> 3;          // 0..31  (also interior-load row)
  const int wq = (tid & 7) << 2;    // 0,4,...,28

  // ---- neighbors first (latency hides under the x-tile load) ----
  if (tid < NPER * 9) {  // 72 scalars
    int nn = tid / 9;
    int k  = tid - nn * 9;
    nbs[nn * 12 + k] = nb[(size_t)(ns * NPER + nn) * (C * 9) + c * 9 + k];
  }

  // ---- x tile: 1 vector LDG per thread + predicated halo zeros ----
  const float* xp = x + (size_t)bc * HW;
  {
    float4 v = *(const float4*)(xp + h * W + wq);
    float* dst = &xs[(h + 1) * 36 + wq + 1];
    dst[0] = v.x; dst[1] = v.y; dst[2] = v.z; dst[3] = v.w;
  }
  if (tid < 132) {  // halo cells: rows 0,33 cols 0..33; cols 0,33 rows 1..32
    int rr, cc;
    if (tid < 68)        { rr = (tid < 34) ? 0 : 33; cc = (tid < 34) ? tid : tid - 34; }
    else if (tid < 100)  { rr = tid - 68 + 1;  cc = 0; }
    else                 { rr = tid - 100 + 1; cc = 33; }
    xs[rr * 36 + cc] = 0.f;
  }
  __syncthreads();

  // hoist the 3x6 x-window into registers (reused across all NPER n)
  float xv[3][6];
#pragma unroll
  for (int r = 0; r < 3; r++) {
    const float* p = &xs[(h + r) * 36 + wq];
    float4 v4 = *(const float4*)p;
    float2 v2 = *(const float2*)(p + 4);
    xv[r][0] = v4.x; xv[r][1] = v4.y; xv[r][2] = v4.z; xv[r][3] = v4.w;
    xv[r][4] = v2.x; xv[r][5] = v2.y;
  }

  float* outp = out + ((size_t)(b * NUM + ns * NPER) * C + c) * HW + h * W + wq;

#pragma unroll
  for (int nn = 0; nn < NPER; nn++) {
    float4 n0 = *(const float4*)&nbs[nn * 12];
    float4 n1 = *(const float4*)&nbs[nn * 12 + 4];
    float  n8 = nbs[nn * 12 + 8];
    const float nv[9] = {n0.x, n0.y, n0.z, n0.w, n1.x, n1.y, n1.z, n1.w, n8};

    float res[4];
#pragma unroll
    for (int j = 0; j < 4; j++) {
      // tap k -> window coords: r = 2 - k/3, cc = 2 - k%3, read xv[r][cc+j]
      float d[9];
#pragma unroll
      for (int k = 0; k < 9; k++) {
        const int r  = 2 - k / 3;
        const int cc = 2 - k % 3;
        d[k] = xv[r][cc + j] - nv[k];
      }
      // 8-op dual-abs max tree, depth 4
      float t0 = maxabs(d[0], d[1]);
      float t1 = maxabs(d[2], d[3]);
      float t2 = maxabs(d[4], d[5]);
      float t3 = maxabs(d[6], d[7]);
      float u0 = fmaxf(t0, t1);
      float u1 = fmaxf(t2, t3);
      res[j] = fmaxf(u0, fmaxf(u1, fabsf(d[8])));
    }
    *(float4*)outp = make_float4(res[0], res[1], res[2], res[3]);
    outp += (size_t)C * HW;  // next n: channel index advances by C
  }
}

}  // namespace

extern "C" void kernel_launch(void* const* d_in, const int* in_sizes, int n_in,
                              void* d_out, int out_size) {
  const float* x  = (const float*)d_in[0];   // (B,C,H,W) fp32
  const float* nb = (const float*)d_in[1];   // (NUM,C,9) fp32
  float* out = (float*)d_out;                // (B, NUM*C, H, W) fp32
  dim3 grid(B * C, NSPLIT);
  cnn_kernel<<<grid, 256>>>(x, nb, out);
}

// round 5
// speedup vs baseline: 1.0394x; 1.0394x over previous
#include <cuda_runtime.h>

// ConvNearestNeightbor: out[b, n*C+c, h, w] = max_k |x_pad[b,c,h-row,w-col] - nb[n,c,k]|
// Pipe-throughput-bound. R5: subs as FFMA-imm (rt_SMSP=1, 2x FADD throughput) with
// negated neighbors; dual-abs FMNMX trees on alu pipe. NSPLIT back to 2 (R4 post-mortem).

namespace {

constexpr int B = 16, C = 32, H = 32, W = 32, NUM = 32;
constexpr int HW = H * W;
constexpr int NSPLIT = 2;
constexpr int NPER = NUM / NSPLIT;  // 16

// d = x*1.0 + negnk  -> FFMA R,R,IMM,R (imm multiplier form, rt_SMSP=1)
__device__ __forceinline__ float sub_via_ffma(float x, float negnk) {
  float d;
  asm("fma.rn.f32 %0, %1, 0f3F800000, %2;" : "=f"(d) : "f"(x), "f"(negnk));
  return d;
}
// max(|a|,|b|) -> single FMNMX with |src| modifiers on both operands
__device__ __forceinline__ float maxabs(float a, float b) {
  return fmaxf(fabsf(a), fabsf(b));
}

__global__ __launch_bounds__(256) void cnn_kernel(
    const float* __restrict__ x,
    const float* __restrict__ nb,
    float* __restrict__ out) {
  __shared__ __align__(16) float xs[34 * 36];      // halo tile, padded rows (36 floats)
  __shared__ __align__(16) float nbs[NPER * 12];   // 9 taps (negated) padded to 12 -> LDS.128

  const int bc = blockIdx.x;   // 0 .. B*C-1
  const int ns = blockIdx.y;   // 0 .. NSPLIT-1
  const int c  = bc & (C - 1);
  const int b  = bc / C;
  const int tid = threadIdx.x;

  const int h  = tid >> 3;          // 0..31  (also interior-load row)
  const int wq = (tid & 7) << 2;    // 0,4,...,28

  // ---- neighbors first (latency hides under the x-tile load); store NEGATED ----
  if (tid < NPER * 9) {  // 144 scalars
    int nn = tid / 9;
    int k  = tid - nn * 9;
    nbs[nn * 12 + k] = -nb[(size_t)(ns * NPER + nn) * (C * 9) + c * 9 + k];
  }

  // ---- x tile: 1 vector LDG per thread + predicated halo zeros ----
  const float* xp = x + (size_t)bc * HW;
  {
    float4 v = *(const float4*)(xp + h * W + wq);
    float* dst = &xs[(h + 1) * 36 + wq + 1];
    dst[0] = v.x; dst[1] = v.y; dst[2] = v.z; dst[3] = v.w;
  }
  if (tid < 132) {  // halo cells: rows 0,33 cols 0..33; cols 0,33 rows 1..32
    int rr, cc;
    if (tid < 68)        { rr = (tid < 34) ? 0 : 33; cc = (tid < 34) ? tid : tid - 34; }
    else if (tid < 100)  { rr = tid - 68 + 1;  cc = 0; }
    else                 { rr = tid - 100 + 1; cc = 33; }
    xs[rr * 36 + cc] = 0.f;
  }
  __syncthreads();

  // hoist the 3x6 x-window into registers (reused across all NPER n)
  float xv[3][6];
#pragma unroll
  for (int r = 0; r < 3; r++) {
    const float* p = &xs[(h + r) * 36 + wq];
    float4 v4 = *(const float4*)p;
    float2 v2 = *(const float2*)(p + 4);
    xv[r][0] = v4.x; xv[r][1] = v4.y; xv[r][2] = v4.z; xv[r][3] = v4.w;
    xv[r][4] = v2.x; xv[r][5] = v2.y;
  }

  float* outp = out + ((size_t)(b * NUM + ns * NPER) * C + c) * HW + h * W + wq;

#pragma unroll 4
  for (int nn = 0; nn < NPER; nn++) {
    float4 n0 = *(const float4*)&nbs[nn * 12];
    float4 n1 = *(const float4*)&nbs[nn * 12 + 4];
    float  n8 = nbs[nn * 12 + 8];
    const float nv[9] = {n0.x, n0.y, n0.z, n0.w, n1.x, n1.y, n1.z, n1.w, n8};  // negated

    float res[4];
#pragma unroll
    for (int j = 0; j < 4; j++) {
      // tap k -> window coords: r = 2 - k/3, cc = 2 - k%3, read xv[r][cc+j]
      float d[9];
#pragma unroll
      for (int k = 0; k < 9; k++) {
        const int r  = 2 - k / 3;
        const int cc = 2 - k % 3;
        d[k] = sub_via_ffma(xv[r][cc + j], nv[k]);   // FFMA-imm: x*1.0 + (-nk)
      }
      // 8-op dual-abs max tree, depth 4
      float t0 = maxabs(d[0], d[1]);
      float t1 = maxabs(d[2], d[3]);
      float t2 = maxabs(d[4], d[5]);
      float t3 = maxabs(d[6], d[7]);
      float u0 = fmaxf(t0, t1);
      float u1 = fmaxf(t2, t3);
      res[j] = fmaxf(u0, fmaxf(u1, fabsf(d[8])));
    }
    *(float4*)outp = make_float4(res[0], res[1], res[2], res[3]);
    outp += (size_t)C * HW;  // next n: channel index advances by C
  }
}

}  // namespace

extern "C" void kernel_launch(void* const* d_in, const int* in_sizes, int n_in,
                              void* d_out, int out_size) {
  const float* x  = (const float*)d_in[0];   // (B,C,H,W) fp32
  const float* nb = (const float*)d_in[1];   // (NUM,C,9) fp32
  float* out = (float*)d_out;                // (B, NUM*C, H, W) fp32
  dim3 grid(B * C, NSPLIT);
  cnn_kernel<<<grid, 256>>>(x, nb, out);
}

// round 6
// speedup vs baseline: 1.1210x; 1.0786x over previous
#include <cuda_runtime.h>

// ConvNearestNeightbor: out[b, n*C+c, h, w] = max_k |x_pad[b,c,h-row,w-col] - nb[n,c,k]|
// fma-pipe + issue-port co-bound. R6: force FFMA-imm form (rt_SMSP=1, 2x FADD tput)
// with multiplier 1.0000001 so ptxas CANNOT canonicalize back to FADD.
// (R5 used 1.0 exactly -> folded to FADD -> fma pipe % unchanged. rel_err==0.0 was the tell.)

namespace {

constexpr int B = 16, C = 32, H = 32, W = 32, NUM = 32;
constexpr int HW = H * W;
constexpr int NSPLIT = 2;
constexpr int NPER = NUM / NSPLIT;  // 16

// d = x*(1+2^-23) + negnk  -> FFMA R,R,IMM,R (imm-multiplier form, rt_SMSP=1).
// Multiplier != 1.0 exactly, so ptxas must keep the FFMA. Error ~1.2e-7*|x|.
__device__ __forceinline__ float sub_via_ffma(float x, float negnk) {
  float d;
  asm("fma.rn.f32 %0, %1, 0f3F800001, %2;" : "=f"(d) : "f"(x), "f"(negnk));
  return d;
}
// max(|a|,|b|) -> single FMNMX with |src| modifiers on both operands (alu pipe)
__device__ __forceinline__ float maxabs(float a, float b) {
  return fmaxf(fabsf(a), fabsf(b));
}

__global__ __launch_bounds__(256) void cnn_kernel(
    const float* __restrict__ x,
    const float* __restrict__ nb,
    float* __restrict__ out) {
  __shared__ __align__(16) float xs[34 * 36];      // halo tile, padded rows (36 floats)
  __shared__ __align__(16) float nbs[NPER * 12];   // 9 taps (negated) padded to 12 -> LDS.128

  const int bc = blockIdx.x;   // 0 .. B*C-1
  const int ns = blockIdx.y;   // 0 .. NSPLIT-1
  const int c  = bc & (C - 1);
  const int b  = bc / C;
  const int tid = threadIdx.x;

  const int h  = tid >> 3;          // 0..31  (also interior-load row)
  const int wq = (tid & 7) << 2;    // 0,4,...,28

  // ---- neighbors first (latency hides under the x-tile load); store NEGATED ----
  if (tid < NPER * 9) {  // 144 scalars
    int nn = tid / 9;
    int k  = tid - nn * 9;
    nbs[nn * 12 + k] = -nb[(size_t)(ns * NPER + nn) * (C * 9) + c * 9 + k];
  }

  // ---- x tile: 1 vector LDG per thread + predicated halo zeros ----
  const float* xp = x + (size_t)bc * HW;
  {
    float4 v = *(const float4*)(xp + h * W + wq);
    float* dst = &xs[(h + 1) * 36 + wq + 1];
    dst[0] = v.x; dst[1] = v.y; dst[2] = v.z; dst[3] = v.w;
  }
  if (tid < 132) {  // halo cells: rows 0,33 cols 0..33; cols 0,33 rows 1..32
    int rr, cc;
    if (tid < 68)        { rr = (tid < 34) ? 0 : 33; cc = (tid < 34) ? tid : tid - 34; }
    else if (tid < 100)  { rr = tid - 68 + 1;  cc = 0; }
    else                 { rr = tid - 100 + 1; cc = 33; }
    xs[rr * 36 + cc] = 0.f;
  }
  __syncthreads();

  // hoist the 3x6 x-window into registers (reused across all NPER n)
  float xv[3][6];
#pragma unroll
  for (int r = 0; r < 3; r++) {
    const float* p = &xs[(h + r) * 36 + wq];
    float4 v4 = *(const float4*)p;
    float2 v2 = *(const float2*)(p + 4);
    xv[r][0] = v4.x; xv[r][1] = v4.y; xv[r][2] = v4.z; xv[r][3] = v4.w;
    xv[r][4] = v2.x; xv[r][5] = v2.y;
  }

  float* outp = out + ((size_t)(b * NUM + ns * NPER) * C + c) * HW + h * W + wq;

#pragma unroll 4
  for (int nn = 0; nn < NPER; nn++) {
    float4 n0 = *(const float4*)&nbs[nn * 12];
    float4 n1 = *(const float4*)&nbs[nn * 12 + 4];
    float  n8 = nbs[nn * 12 + 8];
    const float nv[9] = {n0.x, n0.y, n0.z, n0.w, n1.x, n1.y, n1.z, n1.w, n8};  // negated

    float res[4];
#pragma unroll
    for (int j = 0; j < 4; j++) {
      // tap k -> window coords: r = 2 - k/3, cc = 2 - k%3, read xv[r][cc+j]
      float d[9];
#pragma unroll
      for (int k = 0; k < 9; k++) {
        const int r  = 2 - k / 3;
        const int cc = 2 - k % 3;
        d[k] = sub_via_ffma(xv[r][cc + j], nv[k]);   // FFMA-imm, rt_SMSP=1
      }
      // 8-op dual-abs max tree, depth 4 (alu pipe)
      float t0 = maxabs(d[0], d[1]);
      float t1 = maxabs(d[2], d[3]);
      float t2 = maxabs(d[4], d[5]);
      float t3 = maxabs(d[6], d[7]);
      float u0 = fmaxf(t0, t1);
      float u1 = fmaxf(t2, t3);
      res[j] = fmaxf(u0, fmaxf(u1, fabsf(d[8])));
    }
    *(float4*)outp = make_float4(res[0], res[1], res[2], res[3]);
    outp += (size_t)C * HW;  // next n: channel index advances by C
  }
}

}  // namespace

extern "C" void kernel_launch(void* const* d_in, const int* in_sizes, int n_in,
                              void* d_out, int out_size) {
  const float* x  = (const float*)d_in[0];   // (B,C,H,W) fp32
  const float* nb = (const float*)d_in[1];   // (NUM,C,9) fp32
  float* out = (float*)d_out;                // (B, NUM*C, H, W) fp32
  dim3 grid(B * C, NSPLIT);
  cnn_kernel<<<grid, 256>>>(x, nb, out);
}

// round 7
// speedup vs baseline: 1.1355x; 1.0129x over previous
#include <cuda_runtime.h>

// ConvNearestNeightbor: out[b, n*C+c, h, w] = max_k |x_pad[b,c,h-row,w-col] - nb[n,c,k]|
// Issue-slot bound. R7: real packed FFMA2 via PTX fma.rn.f32x2 (the form SASS_QUICKREF
// says maps to HW FFMA2) -> 36 fma ops/iter become 18. Multiplier 1+2^-23 prevents
// canonicalization (rel_err ~1.2e-7, fine vs 1e-3). Incremental pairwise max tree
// bounds register pressure (R2 post-mortem).

namespace {

constexpr int B = 16, C = 32, H = 32, W = 32, NUM = 32;
constexpr int HW = H * W;
constexpr int NSPLIT = 2;
constexpr int NPER = NUM / NSPLIT;  // 16

using ull = unsigned long long;

__device__ __forceinline__ ull fma2(ull a, ull b, ull c) {
  ull r;
  asm("fma.rn.f32x2 %0, %1, %2, %3;" : "=l"(r) : "l"(a), "l"(b), "l"(c));
  return r;
}
__device__ __forceinline__ ull pack2(float lo, float hi) {
  ull r;
  asm("mov.b64 %0, {%1, %2};" : "=l"(r) : "f"(lo), "f"(hi));
  return r;
}
__device__ __forceinline__ void unp2(ull v, float& lo, float& hi) {
  asm("mov.b64 {%0, %1}, %2;" : "=f"(lo), "=f"(hi) : "l"(v));
}
// max(|a|,|b|) -> single FMNMX with |src| modifiers (alu pipe)
__device__ __forceinline__ float maxabs(float a, float b) {
  return fmaxf(fabsf(a), fabsf(b));
}

// {1+2^-23, 1+2^-23} packed — not exactly 1.0 so ptxas can't fold the FFMA2.
__device__ constexpr ull ONE2 = 0x3F8000013F800001ULL;

// tap k -> window coords
__device__ constexpr int RK[9]  = {2, 2, 2, 1, 1, 1, 0, 0, 0};
__device__ constexpr int CCK[9] = {2, 1, 0, 2, 1, 0, 2, 1, 0};

__global__ __launch_bounds__(256) void cnn_kernel(
    const float* __restrict__ x,
    const float* __restrict__ nb,
    float* __restrict__ out) {
  __shared__ __align__(16) float xs[34 * 36];        // halo tile, padded rows
  __shared__ __align__(8) float2 nbs2[NPER][9];      // negated + duplicated -> LDS.64

  const int bc = blockIdx.x;   // 0 .. B*C-1
  const int ns = blockIdx.y;   // 0 .. NSPLIT-1
  const int c  = bc & (C - 1);
  const int b  = bc / C;
  const int tid = threadIdx.x;

  const int h  = tid >> 3;          // 0..31
  const int wq = (tid & 7) << 2;    // 0,4,...,28

  // ---- neighbors first (latency hides under x-tile load); negated + duplicated ----
  if (tid < NPER * 9) {  // 144
    int nn = tid / 9;
    int k  = tid - nn * 9;
    float v = -nb[(size_t)(ns * NPER + nn) * (C * 9) + c * 9 + k];
    nbs2[nn][k] = make_float2(v, v);
  }

  // ---- x tile: 1 vector LDG per thread + predicated halo zeros ----
  const float* xp = x + (size_t)bc * HW;
  {
    float4 v = *(const float4*)(xp + h * W + wq);
    float* dst = &xs[(h + 1) * 36 + wq + 1];
    dst[0] = v.x; dst[1] = v.y; dst[2] = v.z; dst[3] = v.w;
  }
  if (tid < 132) {  // halo: rows 0,33 cols 0..33; cols 0,33 rows 1..32
    int rr, cc;
    if (tid < 68)        { rr = (tid < 34) ? 0 : 33; cc = (tid < 34) ? tid : tid - 34; }
    else if (tid < 100)  { rr = tid - 68 + 1;  cc = 0; }
    else                 { rr = tid - 100 + 1; cc = 33; }
    xs[rr * 36 + cc] = 0.f;
  }
  __syncthreads();

  // hoist 3x6 window, pre-packed into 5 sliding pairs per row:
  // pr[r][i] = {xv[r][i], xv[r][i+1]}  (pairs amortized over all 16 n-iters)
  ull pr[3][5];
#pragma unroll
  for (int r = 0; r < 3; r++) {
    const float* p = &xs[(h + r) * 36 + wq];
    float4 v4 = *(const float4*)p;
    float2 v2 = *(const float2*)(p + 4);
    float x0 = v4.x, x1 = v4.y, x2 = v4.z, x3 = v4.w, x4 = v2.x, x5 = v2.y;
    pr[r][0] = pack2(x0, x1);
    pr[r][1] = pack2(x1, x2);
    pr[r][2] = pack2(x2, x3);
    pr[r][3] = pack2(x3, x4);
    pr[r][4] = pack2(x4, x5);
  }

  float* outp = out + ((size_t)(b * NUM + ns * NPER) * C + c) * HW + h * W + wq;

#pragma unroll 4
  for (int nn = 0; nn < NPER; nn++) {
    const float2* nrow = nbs2[nn];
    float u0, u1, u2, u3;

    // taps in pairs (0,1),(2,3),(4,5),(6,7); tap 8 folded at the end
#pragma unroll
    for (int kp = 0; kp < 4; kp++) {
      const int ka = 2 * kp, kb = 2 * kp + 1;
      ull na = *(const ull*)&nrow[ka];
      ull nb_ = *(const ull*)&nrow[kb];
      // tap ka: outputs (0,1) and (2,3)
      ull a01 = fma2(pr[RK[ka]][CCK[ka]],     ONE2, na);
      ull a23 = fma2(pr[RK[ka]][CCK[ka] + 2], ONE2, na);
      // tap kb
      ull b01 = fma2(pr[RK[kb]][CCK[kb]],     ONE2, nb_);
      ull b23 = fma2(pr[RK[kb]][CCK[kb] + 2], ONE2, nb_);
      float a0, a1, a2, a3, b0, b1, b2, b3;
      unp2(a01, a0, a1); unp2(a23, a2, a3);
      unp2(b01, b0, b1); unp2(b23, b2, b3);
      float t0 = maxabs(a0, b0);
      float t1 = maxabs(a1, b1);
      float t2 = maxabs(a2, b2);
      float t3 = maxabs(a3, b3);
      if (kp == 0) { u0 = t0; u1 = t1; u2 = t2; u3 = t3; }
      else         { u0 = fmaxf(u0, t0); u1 = fmaxf(u1, t1);
                     u2 = fmaxf(u2, t2); u3 = fmaxf(u3, t3); }
    }
    {  // tap 8
      ull n8 = *(const ull*)&nrow[8];
      ull c01 = fma2(pr[RK[8]][CCK[8]],     ONE2, n8);
      ull c23 = fma2(pr[RK[8]][CCK[8] + 2], ONE2, n8);
      float c0, c1, c2, c3;
      unp2(c01, c0, c1); unp2(c23, c2, c3);
      u0 = fmaxf(u0, fabsf(c0));
      u1 = fmaxf(u1, fabsf(c1));
      u2 = fmaxf(u2, fabsf(c2));
      u3 = fmaxf(u3, fabsf(c3));
    }
    *(float4*)outp = make_float4(u0, u1, u2, u3);
    outp += (size_t)C * HW;  // next n
  }
}

}  // namespace

extern "C" void kernel_launch(void* const* d_in, const int* in_sizes, int n_in,
                              void* d_out, int out_size) {
  const float* x  = (const float*)d_in[0];   // (B,C,H,W) fp32
  const float* nb = (const float*)d_in[1];   // (NUM,C,9) fp32
  float* out = (float*)d_out;                // (B, NUM*C, H, W) fp32
  dim3 grid(B * C, NSPLIT);
  cnn_kernel<<<grid, 256>>>(x, nb, out);
}